// round 1
// baseline (speedup 1.0000x reference)
#include <cuda_runtime.h>
#include <cuda_bf16.h>
#include <cstdint>
#include <cstddef>

// Problem constants
#define B_SZ 32
#define T_SZ 2048
#define D_SZ 512
#define TOPK 15
#define M_ROWS (B_SZ * T_SZ)   // 65536

// ---------------- scratch (static device arrays; no allocs allowed) ----------
__device__ float  g_qt[(size_t)B_SZ * D_SZ * T_SZ];   // q transposed [B,D,T]
__device__ float  g_kt[(size_t)B_SZ * D_SZ * T_SZ];   // k transposed [B,D,T]
__device__ float  g_v [(size_t)B_SZ * T_SZ * D_SZ];   // v natural [B,T,D]
__device__ float  g_at[(size_t)B_SZ * D_SZ * T_SZ];   // attn_weights transposed [B,D,T]
__device__ float  g_ao[(size_t)B_SZ * T_SZ * D_SZ];   // softmax * rolled_sum [B,T,D]
__device__ float  g_mean[B_SZ * T_SZ];
__device__ int    g_del[B_SZ * 16];
__device__ float2 g_tw[1024];                          // exp(-2*pi*i*j/2048), j=0..1023

// ---------------- twiddle init ----------------------------------------------
__global__ void tw_init_kernel() {
    int j = blockIdx.x * blockDim.x + threadIdx.x;
    if (j < 1024) {
        float ang = -6.283185307179586f * (float)j / 2048.0f;
        g_tw[j] = make_float2(cosf(ang), sinf(ang));
    }
}

// ---------------- SGEMM: C = A[M,512] @ W[512,512] + bias -------------------
// TOUT=false: C[m,n] natural [M,512]
// TOUT=true : C stored transposed per batch: C[b, n, t], b=m>>11, t=m&2047
template <bool TOUT>
__global__ void __launch_bounds__(256) sgemm_kernel(
    const float* __restrict__ A, const float* __restrict__ W,
    const float* __restrict__ bias, float* __restrict__ C, int M)
{
    const int K = 512, N = 512;
    __shared__ __align__(16) float As[8][128];
    __shared__ __align__(16) float Bs[8][128];

    int tid = threadIdx.x;
    int bm = blockIdx.y * 128;
    int bn = blockIdx.x * 128;

    int a_row = tid >> 1;            // 0..127
    int a_col = (tid & 1) << 2;      // 0 or 4
    int b_row = tid >> 5;            // 0..7
    int b_col = (tid & 31) << 2;     // 0..124

    int tx = tid & 15, ty = tid >> 4;

    float acc[8][8];
#pragma unroll
    for (int i = 0; i < 8; i++)
#pragma unroll
        for (int j = 0; j < 8; j++) acc[i][j] = 0.0f;

    for (int k0 = 0; k0 < K; k0 += 8) {
        float4 av = *(const float4*)(A + (size_t)(bm + a_row) * K + k0 + a_col);
        As[a_col + 0][a_row] = av.x;
        As[a_col + 1][a_row] = av.y;
        As[a_col + 2][a_row] = av.z;
        As[a_col + 3][a_row] = av.w;
        float4 bv = *(const float4*)(W + (size_t)(k0 + b_row) * N + bn + b_col);
        *(float4*)&Bs[b_row][b_col] = bv;
        __syncthreads();
#pragma unroll
        for (int kk = 0; kk < 8; kk++) {
            float4 a0 = *(const float4*)&As[kk][ty * 8];
            float4 a1 = *(const float4*)&As[kk][ty * 8 + 4];
            float4 b0 = *(const float4*)&Bs[kk][tx * 8];
            float4 b1 = *(const float4*)&Bs[kk][tx * 8 + 4];
            float ra[8] = {a0.x, a0.y, a0.z, a0.w, a1.x, a1.y, a1.z, a1.w};
            float rb[8] = {b0.x, b0.y, b0.z, b0.w, b1.x, b1.y, b1.z, b1.w};
#pragma unroll
            for (int i = 0; i < 8; i++)
#pragma unroll
                for (int j = 0; j < 8; j++) acc[i][j] += ra[i] * rb[j];
        }
        __syncthreads();
    }

    if (!TOUT) {
#pragma unroll
        for (int i = 0; i < 8; i++) {
            int m = bm + ty * 8 + i;
#pragma unroll
            for (int j = 0; j < 8; j += 4) {
                int n = bn + tx * 8 + j;
                float4 o = make_float4(acc[i][j] + bias[n],
                                       acc[i][j + 1] + bias[n + 1],
                                       acc[i][j + 2] + bias[n + 2],
                                       acc[i][j + 3] + bias[n + 3]);
                *(float4*)(C + (size_t)m * N + n) = o;
            }
        }
    } else {
#pragma unroll
        for (int j = 0; j < 8; j++) {
            int n = bn + tx * 8 + j;
            float bb = bias[n];
#pragma unroll
            for (int i = 0; i < 8; i += 4) {
                int m = bm + ty * 8 + i;
                size_t off = (size_t)(m >> 11) * ((size_t)D_SZ * T_SZ)
                           + (size_t)n * T_SZ + (m & (T_SZ - 1));
                float4 o = make_float4(acc[i][j] + bb, acc[i + 1][j] + bb,
                                       acc[i + 2][j] + bb, acc[i + 3][j] + bb);
                *(float4*)(C + off) = o;
            }
        }
    }
}

// ---------------- FFT correlation kernel ------------------------------------
// Stockham radix-2, out-of-place ping-pong, autosorting. 11 stages for N=2048.
__device__ float2* fft2048_sm(float2* x, float2* y, bool inv)
{
    int sh = 0;
    for (int nn = 2048; nn >= 2; nn >>= 1) {
        int m = nn >> 1;
        int tmul = 2048 / nn;
        int s = 1 << sh;
        for (int i = threadIdx.x; i < 1024; i += 256) {
            int q = i & (s - 1);
            int p = i >> sh;
            float2 w = g_tw[p * tmul];
            float wy = inv ? -w.y : w.y;
            float2 a = x[q + (p << sh)];
            float2 b = x[q + ((p + m) << sh)];
            float2 u = make_float2(a.x + b.x, a.y + b.y);
            float2 v = make_float2(a.x - b.x, a.y - b.y);
            float2 o = make_float2(v.x * w.x - v.y * wy, v.x * wy + v.y * w.x);
            y[q + ((2 * p) << sh)] = u;
            y[q + ((2 * p + 1) << sh)] = o;
        }
        __syncthreads();
        float2* t = x; x = y; y = t;
        sh++;
    }
    return x;  // result buffer after 11 swaps
}

__global__ void __launch_bounds__(256) fftcorr_kernel(
    const float* __restrict__ qt, const float* __restrict__ kt,
    float* __restrict__ attn)
{
    __shared__ float2 bufA[2048];
    __shared__ float2 bufB[2048];
    int c = blockIdx.x;  // channel = b*512 + d
    const float* qp = qt + (size_t)c * T_SZ;
    const float* kp = kt + (size_t)c * T_SZ;

    for (int i = threadIdx.x; i < 2048; i += 256)
        bufA[i] = make_float2(qp[i], kp[i]);
    __syncthreads();

    float2* Z = fft2048_sm(bufA, bufB, false);
    float2* S = (Z == bufA) ? bufB : bufA;

    // z = q + i*k  =>  Q[f] = (Z[f]+conj(Z[-f]))/2, K[f] = -i/2*(Z[f]-conj(Z[-f]))
    // P[f] = Q[f] * conj(K[f])   (Hermitian)
    for (int i = threadIdx.x; i < 2048; i += 256) {
        float2 zf = Z[i];
        float2 zc = Z[(2048 - i) & 2047];
        float2 Q  = make_float2(0.5f * (zf.x + zc.x), 0.5f * (zf.y - zc.y));
        float2 Dm = make_float2(0.5f * (zf.x - zc.x), 0.5f * (zf.y + zc.y));
        float2 Kc = make_float2(Dm.y, -Dm.x);  // -i * Dm
        S[i] = make_float2(Q.x * Kc.x + Q.y * Kc.y, Q.y * Kc.x - Q.x * Kc.y);
    }
    __syncthreads();

    float2* R = fft2048_sm(S, Z, true);
    float* op = attn + (size_t)c * T_SZ;
    const float inv = 1.0f / 2048.0f;
    for (int i = threadIdx.x; i < 2048; i += 256)
        op[i] = R[i].x * inv;
}

// ---------------- mean over d (attn stored [B,D,T]) --------------------------
__global__ void __launch_bounds__(256) mean_kernel(
    const float* __restrict__ attn, float* __restrict__ meanv)
{
    int b = blockIdx.y;
    int t = blockIdx.x * 256 + threadIdx.x;
    const float* ap = attn + (size_t)b * D_SZ * T_SZ + t;
    float acc = 0.0f;
    for (int d = 0; d < D_SZ; d++) acc += ap[(size_t)d * T_SZ];
    meanv[b * T_SZ + t] = acc * (1.0f / (float)D_SZ);
}

// ---------------- top-k (k=15) per batch -------------------------------------
__global__ void __launch_bounds__(256) topk_kernel(
    const float* __restrict__ meanv, int* __restrict__ delays)
{
    __shared__ float sv[T_SZ];
    __shared__ float rv[256];
    __shared__ int   ri[256];
    int b = blockIdx.x, tid = threadIdx.x;
    for (int i = tid; i < T_SZ; i += 256) sv[i] = meanv[b * T_SZ + i];
    __syncthreads();
    for (int k = 0; k < TOPK; k++) {
        float best = -3.4e38f; int bi = 0;
        for (int i = tid; i < T_SZ; i += 256) {
            float v = sv[i];
            if (v > best) { best = v; bi = i; }
        }
        rv[tid] = best; ri[tid] = bi;
        __syncthreads();
        for (int off = 128; off > 0; off >>= 1) {
            if (tid < off) {
                bool take = (rv[tid + off] > rv[tid]) ||
                            (rv[tid + off] == rv[tid] && ri[tid + off] < ri[tid]);
                if (take) { rv[tid] = rv[tid + off]; ri[tid] = ri[tid + off]; }
            }
            __syncthreads();
        }
        if (tid == 0) { delays[b * 16 + k] = ri[0]; sv[ri[0]] = -3.4e38f; }
        __syncthreads();
    }
}

// ---------------- fused softmax(d) * rolled_sum ------------------------------
// out[b,t,d] = softmax_d(attn[b,t,:])[d] * sum_k v[b,(t-del_k)%T,d]
__global__ void __launch_bounds__(256) fuse_kernel(
    const float* __restrict__ attn,   // [B,D,T]
    const float* __restrict__ v,      // [B,T,D]
    const int*   __restrict__ delays, // [B,16]
    float* __restrict__ out)          // [B,T,D]
{
    extern __shared__ float tile[];            // [512][33]
    __shared__ float smax[32], ssum[32];
    __shared__ int   sidx[32][TOPK];
    const int PAD = 33;

    int b  = blockIdx.y;
    int t0 = blockIdx.x * 32;
    int tid = threadIdx.x;

    const float* ap = attn + (size_t)b * D_SZ * T_SZ;

    // load attn tile [512 d][32 t], coalesced along t
    for (int i = tid; i < D_SZ * 32; i += 256) {
        int d = i >> 5, t = i & 31;
        tile[d * PAD + t] = ap[(size_t)d * T_SZ + t0 + t];
    }
    // precompute source rows for the 15 rolls
    for (int i = tid; i < 32 * TOPK; i += 256) {
        int t = i / TOPK, k = i - t * TOPK;
        sidx[t][k] = (t0 + t - delays[b * 16 + k]) & (T_SZ - 1);
    }
    __syncthreads();

    // per-t softmax stats: warp w handles t = w*4 + lane/8; 8 lanes per t
    {
        int w = tid >> 5, lane = tid & 31;
        int t = w * 4 + (lane >> 3);
        int sub = lane & 7;
        float mx = -3.4e38f;
        for (int d = sub; d < D_SZ; d += 8) mx = fmaxf(mx, tile[d * PAD + t]);
#pragma unroll
        for (int o = 4; o > 0; o >>= 1) mx = fmaxf(mx, __shfl_xor_sync(0xffffffffu, mx, o));
        float se = 0.0f;
        for (int d = sub; d < D_SZ; d += 8) {
            float e = __expf(tile[d * PAD + t] - mx);
            tile[d * PAD + t] = e;   // cache exp value
            se += e;
        }
#pragma unroll
        for (int o = 4; o > 0; o >>= 1) se += __shfl_xor_sync(0xffffffffu, se, o);
        if (sub == 0) { smax[t] = mx; ssum[t] = 1.0f / se; }
    }
    __syncthreads();

    const float* vb = v + (size_t)b * T_SZ * D_SZ;
    float* ob = out + ((size_t)b * T_SZ + t0) * D_SZ;

    for (int j = 0; j < 64; j++) {
        int idx = tid + j * 256;
        int d = idx & (D_SZ - 1), tt = idx >> 9;
        float r = 0.0f;
#pragma unroll
        for (int k = 0; k < TOPK; k++)
            r += vb[(size_t)sidx[tt][k] * D_SZ + d];
        float sm = tile[d * PAD + tt] * ssum[tt];
        ob[(size_t)tt * D_SZ + d] = sm * r;
    }
}

// ---------------- launch -----------------------------------------------------
extern "C" void kernel_launch(void* const* d_in, const int* in_sizes, int n_in,
                              void* d_out, int out_size)
{
    const float* query  = (const float*)d_in[0];
    const float* key_in = (const float*)d_in[1];
    const float* value  = (const float*)d_in[2];
    const float* Wq = (const float*)d_in[3];
    const float* bq = (const float*)d_in[4];
    const float* Wk = (const float*)d_in[5];
    const float* bk = (const float*)d_in[6];
    const float* Wv = (const float*)d_in[7];
    const float* bv = (const float*)d_in[8];
    const float* Wo = (const float*)d_in[9];
    const float* bo = (const float*)d_in[10];
    float* out = (float*)d_out;

    float *qt, *kt, *v, *attn, *ao, *meanv;
    int* del;
    cudaGetSymbolAddress((void**)&qt,    g_qt);
    cudaGetSymbolAddress((void**)&kt,    g_kt);
    cudaGetSymbolAddress((void**)&v,     g_v);
    cudaGetSymbolAddress((void**)&attn,  g_at);
    cudaGetSymbolAddress((void**)&ao,    g_ao);
    cudaGetSymbolAddress((void**)&meanv, g_mean);
    cudaGetSymbolAddress((void**)&del,   g_del);

    cudaFuncSetAttribute(fuse_kernel,
                         cudaFuncAttributeMaxDynamicSharedMemorySize, 70000);

    dim3 ggrid(4, M_ROWS / 128);

    tw_init_kernel<<<4, 256>>>();
    sgemm_kernel<true ><<<ggrid, 256>>>(query,  Wq, bq, qt, M_ROWS);
    sgemm_kernel<true ><<<ggrid, 256>>>(key_in, Wk, bk, kt, M_ROWS);
    sgemm_kernel<false><<<ggrid, 256>>>(value,  Wv, bv, v,  M_ROWS);
    fftcorr_kernel<<<B_SZ * D_SZ, 256>>>(qt, kt, attn);
    mean_kernel<<<dim3(T_SZ / 256, B_SZ), 256>>>(attn, meanv);
    topk_kernel<<<B_SZ, 256>>>(meanv, del);
    fuse_kernel<<<dim3(T_SZ / 32, B_SZ), 256, 512 * 33 * 4>>>(attn, v, del, ao);
    sgemm_kernel<false><<<ggrid, 256>>>(ao, Wo, bo, out, M_ROWS);
}

// round 4
// speedup vs baseline: 1.7326x; 1.7326x over previous
#include <cuda_runtime.h>
#include <cuda_bf16.h>
#include <cstdint>
#include <cstddef>

// Problem constants
#define B_SZ 32
#define T_SZ 2048
#define D_SZ 512
#define TOPK 15
#define M_ROWS (B_SZ * T_SZ)   // 65536

// ---------------- scratch (static device arrays; no allocs allowed) ----------
__device__ float  g_qt[(size_t)B_SZ * D_SZ * T_SZ];   // q transposed [B,D,T]
__device__ float  g_kt[(size_t)B_SZ * D_SZ * T_SZ];   // k transposed [B,D,T]
__device__ float  g_v [(size_t)B_SZ * T_SZ * D_SZ];   // v natural [B,T,D]
__device__ float  g_at[(size_t)B_SZ * D_SZ * T_SZ];   // attn_weights transposed [B,D,T]
__device__ float  g_mean[B_SZ * T_SZ];
__device__ int    g_del[B_SZ * 16];
__device__ float2 g_tw[1024];
__device__ __nv_bfloat16 g_wh[4][512 * 512];              // W^T hi [N,K]
__device__ __nv_bfloat16 g_wl[4][512 * 512];              // W^T lo [N,K]
__device__ __nv_bfloat16 g_ah[(size_t)M_ROWS * 512];      // A hi (reused per GEMM)
__device__ __nv_bfloat16 g_al[(size_t)M_ROWS * 512];      // A lo

// ======================= helpers =============================================
__device__ __forceinline__ uint32_t smem_u32(const void* p) {
    uint32_t a;
    asm("{ .reg .u64 t; cvta.to.shared.u64 t, %1; cvt.u32.u64 %0, t; }"
        : "=r"(a) : "l"(p));
    return a;
}
__device__ __forceinline__ uint32_t pack_bf2(__nv_bfloat16 a, __nv_bfloat16 b) {
    return (uint32_t)__bfloat16_as_ushort(a) | ((uint32_t)__bfloat16_as_ushort(b) << 16);
}
__device__ __forceinline__ void cpasync16(uint32_t saddr, const void* gaddr) {
    asm volatile("cp.async.cg.shared.global [%0], [%1], 16;"
                 :: "r"(saddr), "l"(gaddr));
}
#define CP_COMMIT() asm volatile("cp.async.commit_group;" ::: "memory")
#define CP_WAIT1()  asm volatile("cp.async.wait_group 1;" ::: "memory")

__device__ __forceinline__ void ldsm_x4(uint32_t (&r)[4], uint32_t addr) {
    asm volatile("ldmatrix.sync.aligned.m8n8.x4.shared.b16 {%0,%1,%2,%3}, [%4];"
                 : "=r"(r[0]), "=r"(r[1]), "=r"(r[2]), "=r"(r[3]) : "r"(addr));
}
__device__ __forceinline__ void mma_bf16(float (&c)[4], const uint32_t (&a)[4],
                                         const uint32_t* b) {
    asm volatile("mma.sync.aligned.m16n8k16.row.col.f32.bf16.bf16.f32 "
                 "{%0,%1,%2,%3}, {%4,%5,%6,%7}, {%8,%9}, {%0,%1,%2,%3};"
                 : "+f"(c[0]), "+f"(c[1]), "+f"(c[2]), "+f"(c[3])
                 : "r"(a[0]), "r"(a[1]), "r"(a[2]), "r"(a[3]),
                   "r"(b[0]), "r"(b[1]));
}

// ---------------- twiddle init ----------------------------------------------
__global__ void tw_init_kernel() {
    int j = blockIdx.x * blockDim.x + threadIdx.x;
    if (j < 1024) {
        float ang = -6.283185307179586f * (float)j / 2048.0f;
        g_tw[j] = make_float2(cosf(ang), sinf(ang));
    }
}

// ---------------- W transpose + bf16 split ----------------------------------
__global__ void wsplit_kernel(const float* __restrict__ W,
                              __nv_bfloat16* __restrict__ Wh,
                              __nv_bfloat16* __restrict__ Wl)
{
    __shared__ float tile[32][33];
    int bx = blockIdx.x * 32, by = blockIdx.y * 32;
    int tx = threadIdx.x, ty = threadIdx.y;
    for (int i = ty; i < 32; i += 8)
        tile[i][tx] = W[(size_t)(by + i) * 512 + bx + tx];
    __syncthreads();
    for (int i = ty; i < 32; i += 8) {
        float x = tile[tx][i];                 // W[by+tx][bx+i]
        __nv_bfloat16 h = __float2bfloat16(x);
        float r = x - __bfloat162float(h);
        size_t o = (size_t)(bx + i) * 512 + by + tx;   // [n][k]
        Wh[o] = h;
        Wl[o] = __float2bfloat16(r);
    }
}

// ---------------- A fp32 -> split bf16 ---------------------------------------
__global__ void __launch_bounds__(256) asplit_kernel(
    const float4* __restrict__ A, uint2* __restrict__ Ah, uint2* __restrict__ Al)
{
    size_t i = (size_t)blockIdx.x * 256 + threadIdx.x;
    float4 x = A[i];
    __nv_bfloat16 h0 = __float2bfloat16(x.x);
    __nv_bfloat16 h1 = __float2bfloat16(x.y);
    __nv_bfloat16 h2 = __float2bfloat16(x.z);
    __nv_bfloat16 h3 = __float2bfloat16(x.w);
    __nv_bfloat16 l0 = __float2bfloat16(x.x - __bfloat162float(h0));
    __nv_bfloat16 l1 = __float2bfloat16(x.y - __bfloat162float(h1));
    __nv_bfloat16 l2 = __float2bfloat16(x.z - __bfloat162float(h2));
    __nv_bfloat16 l3 = __float2bfloat16(x.w - __bfloat162float(h3));
    Ah[i] = make_uint2(pack_bf2(h0, h1), pack_bf2(h2, h3));
    Al[i] = make_uint2(pack_bf2(l0, l1), pack_bf2(l2, l3));
}

// ---------------- HMMA split-bf16 GEMM ---------------------------------------
// C[M,512] = (Ah+Al)[M,512] @ (Wh+Wl)^T[N,K] + bias
// CTA 128x128, 8 warps (2m x 4n), warp tile 64x32, K-chunk 32, double buffer.
#define TILE_B  10240u              // 128 rows * 80B
#define STAGE_B (4u * TILE_B)       // Ah,Al,Wh,Wl
#define GSM_B   (2u * STAGE_B)      // 81920

__device__ __forceinline__ void gemm_issue(
    uint32_t sdst,
    const __nv_bfloat16* __restrict__ Ah, const __nv_bfloat16* __restrict__ Al,
    const __nv_bfloat16* __restrict__ Wh, const __nv_bfloat16* __restrict__ Wl,
    int bm, int n0, int k0, int r0, int c0)
{
#pragma unroll
    for (int half = 0; half < 2; half++) {
        int row = r0 + half * 64;
        uint32_t so = (uint32_t)row * 80u + (uint32_t)c0 * 16u;
        size_t ga = (size_t)(bm + row) * 512 + k0 + c0 * 8;
        size_t gw = (size_t)(n0 + row) * 512 + k0 + c0 * 8;
        cpasync16(sdst + 0u * TILE_B + so, Ah + ga);
        cpasync16(sdst + 1u * TILE_B + so, Al + ga);
        cpasync16(sdst + 2u * TILE_B + so, Wh + gw);
        cpasync16(sdst + 3u * TILE_B + so, Wl + gw);
    }
}

template <bool TOUT>
__global__ void __launch_bounds__(256, 1) mma_gemm(
    const __nv_bfloat16* __restrict__ Ah, const __nv_bfloat16* __restrict__ Al,
    const __nv_bfloat16* __restrict__ Wh, const __nv_bfloat16* __restrict__ Wl,
    const float* __restrict__ bias, float* __restrict__ C)
{
    extern __shared__ char smraw[];
    const int tid  = threadIdx.x;
    const int lane = tid & 31, wid = tid >> 5;
    const int wm = (wid >> 2) * 64;
    const int wn = (wid & 3) * 32;
    const int bm = blockIdx.y * 128;
    const int n0 = blockIdx.x * 128;

    const uint32_t sbase = smem_u32(smraw);
    const int r0 = tid >> 2, c0 = tid & 3;

    float acc[4][4][4];
#pragma unroll
    for (int i = 0; i < 4; i++)
#pragma unroll
        for (int j = 0; j < 4; j++)
#pragma unroll
            for (int q = 0; q < 4; q++) acc[i][j][q] = 0.0f;

    gemm_issue(sbase, Ah, Al, Wh, Wl, bm, n0, 0, r0, c0);
    CP_COMMIT();

    const uint32_t rowsel = (uint32_t)(lane & 15);
    const uint32_t koff   = (uint32_t)(lane >> 4) * 16u;

    for (int it = 0; it < 16; it++) {
        if (it + 1 < 16)
            gemm_issue(sbase + (uint32_t)((it + 1) & 1) * STAGE_B,
                       Ah, Al, Wh, Wl, bm, n0, (it + 1) * 32, r0, c0);
        CP_COMMIT();
        CP_WAIT1();
        __syncthreads();

        const uint32_t s = sbase + (uint32_t)(it & 1) * STAGE_B;
#pragma unroll
        for (int ks = 0; ks < 2; ks++) {
            const uint32_t kc = (uint32_t)(2 * ks) * 16u + koff;
            uint32_t ahf[4][4], alf[4][4];
#pragma unroll
            for (int mt = 0; mt < 4; mt++) {
                uint32_t ro = (uint32_t)(wm + mt * 16 + rowsel) * 80u + kc;
                ldsm_x4(ahf[mt], s + 0u * TILE_B + ro);
                ldsm_x4(alf[mt], s + 1u * TILE_B + ro);
            }
            // B fragments: ldmatrix.x4 yields matrices in order
            //   t4[0]=(n0-7,k0-7) t4[1]=(n8-15,k0-7) t4[2]=(n0-7,k8-15) t4[3]=(n8-15,k8-15)
            // mma needs per-n-group {k0-7, k8-15}: group0={t4[0],t4[2]}, group1={t4[1],t4[3]}
            uint32_t bhf[4][2], blf[4][2];
#pragma unroll
            for (int ng = 0; ng < 2; ng++) {
                uint32_t ro = (uint32_t)(wn + ng * 16 + rowsel) * 80u + kc;
                uint32_t t4[4];
                ldsm_x4(t4, s + 2u * TILE_B + ro);
                bhf[ng * 2][0]     = t4[0]; bhf[ng * 2][1]     = t4[2];
                bhf[ng * 2 + 1][0] = t4[1]; bhf[ng * 2 + 1][1] = t4[3];
                ldsm_x4(t4, s + 3u * TILE_B + ro);
                blf[ng * 2][0]     = t4[0]; blf[ng * 2][1]     = t4[2];
                blf[ng * 2 + 1][0] = t4[1]; blf[ng * 2 + 1][1] = t4[3];
            }
#pragma unroll
            for (int mt = 0; mt < 4; mt++)
#pragma unroll
                for (int nt = 0; nt < 4; nt++) {
                    mma_bf16(acc[mt][nt], ahf[mt], bhf[nt]);
                    mma_bf16(acc[mt][nt], ahf[mt], blf[nt]);
                    mma_bf16(acc[mt][nt], alf[mt], bhf[nt]);
                }
        }
        __syncthreads();
    }

    const int g = lane >> 2, t4x = lane & 3;
    if (!TOUT) {
#pragma unroll
        for (int mt = 0; mt < 4; mt++) {
            int m = bm + wm + mt * 16 + g;
#pragma unroll
            for (int nt = 0; nt < 4; nt++) {
                int n = n0 + wn + nt * 8 + 2 * t4x;
                float b0 = bias[n], b1 = bias[n + 1];
                float2 o0 = make_float2(acc[mt][nt][0] + b0, acc[mt][nt][1] + b1);
                float2 o1 = make_float2(acc[mt][nt][2] + b0, acc[mt][nt][3] + b1);
                *(float2*)(C + (size_t)m * 512 + n) = o0;
                *(float2*)(C + (size_t)(m + 8) * 512 + n) = o1;
            }
        }
    } else {
        // store C[b, n, t] (t contiguous) via smem transpose staging
        float* tb = (float*)smraw;          // [128 n][132 m]
#pragma unroll
        for (int mt = 0; mt < 4; mt++) {
            int ml = wm + mt * 16 + g;
#pragma unroll
            for (int nt = 0; nt < 4; nt++) {
                int nl = wn + nt * 8 + 2 * t4x;
                float b0 = bias[n0 + nl], b1 = bias[n0 + nl + 1];
                tb[nl * 132 + ml]           = acc[mt][nt][0] + b0;
                tb[(nl + 1) * 132 + ml]     = acc[mt][nt][1] + b1;
                tb[nl * 132 + ml + 8]       = acc[mt][nt][2] + b0;
                tb[(nl + 1) * 132 + ml + 8] = acc[mt][nt][3] + b1;
            }
        }
        __syncthreads();
        const int b = bm >> 11;
        const int t0 = bm & (T_SZ - 1);
        float* gb = C + (size_t)b * D_SZ * T_SZ + t0;
#pragma unroll
        for (int j = 0; j < 16; j++) {
            int f4 = tid + j * 256;
            int nl = f4 >> 5, m4 = f4 & 31;
            float4 o = *(float4*)&tb[nl * 132 + m4 * 4];
            *(float4*)(gb + (size_t)(n0 + nl) * T_SZ + m4 * 4) = o;
        }
    }
}

// ---------------- FFT correlation kernel ------------------------------------
__device__ float2* fft2048_sm(float2* x, float2* y, bool inv)
{
    int sh = 0;
    for (int nn = 2048; nn >= 2; nn >>= 1) {
        int m = nn >> 1;
        int tmul = 2048 / nn;
        int s = 1 << sh;
        for (int i = threadIdx.x; i < 1024; i += 256) {
            int q = i & (s - 1);
            int p = i >> sh;
            float2 w = g_tw[p * tmul];
            float wy = inv ? -w.y : w.y;
            float2 a = x[q + (p << sh)];
            float2 b = x[q + ((p + m) << sh)];
            float2 u = make_float2(a.x + b.x, a.y + b.y);
            float2 v = make_float2(a.x - b.x, a.y - b.y);
            float2 o = make_float2(v.x * w.x - v.y * wy, v.x * wy + v.y * w.x);
            y[q + ((2 * p) << sh)] = u;
            y[q + ((2 * p + 1) << sh)] = o;
        }
        __syncthreads();
        float2* t = x; x = y; y = t;
        sh++;
    }
    return x;
}

__global__ void __launch_bounds__(256) fftcorr_kernel(
    const float* __restrict__ qt, const float* __restrict__ kt,
    float* __restrict__ attn)
{
    __shared__ float2 bufA[2048];
    __shared__ float2 bufB[2048];
    int c = blockIdx.x;
    const float* qp = qt + (size_t)c * T_SZ;
    const float* kp = kt + (size_t)c * T_SZ;

    for (int i = threadIdx.x; i < 2048; i += 256)
        bufA[i] = make_float2(qp[i], kp[i]);
    __syncthreads();

    float2* Z = fft2048_sm(bufA, bufB, false);
    float2* S = (Z == bufA) ? bufB : bufA;

    for (int i = threadIdx.x; i < 2048; i += 256) {
        float2 zf = Z[i];
        float2 zc = Z[(2048 - i) & 2047];
        float2 Q  = make_float2(0.5f * (zf.x + zc.x), 0.5f * (zf.y - zc.y));
        float2 Dm = make_float2(0.5f * (zf.x - zc.x), 0.5f * (zf.y + zc.y));
        float2 Kc = make_float2(Dm.y, -Dm.x);
        S[i] = make_float2(Q.x * Kc.x + Q.y * Kc.y, Q.y * Kc.x - Q.x * Kc.y);
    }
    __syncthreads();

    float2* R = fft2048_sm(S, Z, true);
    float* op = attn + (size_t)c * T_SZ;
    const float inv = 1.0f / 2048.0f;
    for (int i = threadIdx.x; i < 2048; i += 256)
        op[i] = R[i].x * inv;
}

// ---------------- mean over d -------------------------------------------------
__global__ void __launch_bounds__(256) mean_kernel(
    const float* __restrict__ attn, float* __restrict__ meanv)
{
    int b = blockIdx.y;
    int t = blockIdx.x * 256 + threadIdx.x;
    const float* ap = attn + (size_t)b * D_SZ * T_SZ + t;
    float acc = 0.0f;
    for (int d = 0; d < D_SZ; d++) acc += ap[(size_t)d * T_SZ];
    meanv[b * T_SZ + t] = acc * (1.0f / (float)D_SZ);
}

// ---------------- top-k -------------------------------------------------------
__global__ void __launch_bounds__(256) topk_kernel(
    const float* __restrict__ meanv, int* __restrict__ delays)
{
    __shared__ float sv[T_SZ];
    __shared__ float rv[256];
    __shared__ int   ri[256];
    int b = blockIdx.x, tid = threadIdx.x;
    for (int i = tid; i < T_SZ; i += 256) sv[i] = meanv[b * T_SZ + i];
    __syncthreads();
    for (int k = 0; k < TOPK; k++) {
        float best = -3.4e38f; int bi = 0;
        for (int i = tid; i < T_SZ; i += 256) {
            float v = sv[i];
            if (v > best) { best = v; bi = i; }
        }
        rv[tid] = best; ri[tid] = bi;
        __syncthreads();
        for (int off = 128; off > 0; off >>= 1) {
            if (tid < off) {
                bool take = (rv[tid + off] > rv[tid]) ||
                            (rv[tid + off] == rv[tid] && ri[tid + off] < ri[tid]);
                if (take) { rv[tid] = rv[tid + off]; ri[tid] = ri[tid + off]; }
            }
            __syncthreads();
        }
        if (tid == 0) { delays[b * 16 + k] = ri[0]; sv[ri[0]] = -3.4e38f; }
        __syncthreads();
    }
}

// ---------------- fused softmax(d) * rolled_sum -> split bf16 -----------------
__global__ void __launch_bounds__(256) fuse_kernel(
    const float* __restrict__ attn,   // [B,D,T]
    const float* __restrict__ v,      // [B,T,D]
    const int*   __restrict__ delays, // [B,16]
    __nv_bfloat16* __restrict__ aoh,  // [B,T,D]
    __nv_bfloat16* __restrict__ aol)
{
    extern __shared__ float tile[];
    __shared__ float smax[32], ssum[32];
    __shared__ int   sidx[32][TOPK];
    const int PAD = 33;

    int b  = blockIdx.y;
    int t0 = blockIdx.x * 32;
    int tid = threadIdx.x;

    const float* ap = attn + (size_t)b * D_SZ * T_SZ;

    for (int i = tid; i < D_SZ * 32; i += 256) {
        int d = i >> 5, t = i & 31;
        tile[d * PAD + t] = ap[(size_t)d * T_SZ + t0 + t];
    }
    for (int i = tid; i < 32 * TOPK; i += 256) {
        int t = i / TOPK, k = i - t * TOPK;
        sidx[t][k] = (t0 + t - delays[b * 16 + k]) & (T_SZ - 1);
    }
    __syncthreads();

    {
        int w = tid >> 5, lane = tid & 31;
        int t = w * 4 + (lane >> 3);
        int sub = lane & 7;
        float mx = -3.4e38f;
        for (int d = sub; d < D_SZ; d += 8) mx = fmaxf(mx, tile[d * PAD + t]);
#pragma unroll
        for (int o = 4; o > 0; o >>= 1) mx = fmaxf(mx, __shfl_xor_sync(0xffffffffu, mx, o));
        float se = 0.0f;
        for (int d = sub; d < D_SZ; d += 8) {
            float e = __expf(tile[d * PAD + t] - mx);
            tile[d * PAD + t] = e;
            se += e;
        }
#pragma unroll
        for (int o = 4; o > 0; o >>= 1) se += __shfl_xor_sync(0xffffffffu, se, o);
        if (sub == 0) { smax[t] = mx; ssum[t] = 1.0f / se; }
    }
    __syncthreads();

    const float* vb = v + (size_t)b * T_SZ * D_SZ;
    size_t obase = ((size_t)b * T_SZ + t0) * D_SZ;

    for (int j = 0; j < 64; j++) {
        int idx = tid + j * 256;
        int d = idx & (D_SZ - 1), tt = idx >> 9;
        float r = 0.0f;
#pragma unroll
        for (int k = 0; k < TOPK; k++)
            r += vb[(size_t)sidx[tt][k] * D_SZ + d];
        float val = tile[d * PAD + tt] * ssum[tt] * r;
        __nv_bfloat16 h = __float2bfloat16(val);
        size_t off = obase + (size_t)tt * D_SZ + d;
        aoh[off] = h;
        aol[off] = __float2bfloat16(val - __bfloat162float(h));
    }
}

// ---------------- launch -----------------------------------------------------
extern "C" void kernel_launch(void* const* d_in, const int* in_sizes, int n_in,
                              void* d_out, int out_size)
{
    const float* query  = (const float*)d_in[0];
    const float* key_in = (const float*)d_in[1];
    const float* value  = (const float*)d_in[2];
    const float* Wq = (const float*)d_in[3];
    const float* bq = (const float*)d_in[4];
    const float* Wk = (const float*)d_in[5];
    const float* bk = (const float*)d_in[6];
    const float* Wv = (const float*)d_in[7];
    const float* bv = (const float*)d_in[8];
    const float* Wo = (const float*)d_in[9];
    const float* bo = (const float*)d_in[10];
    float* out = (float*)d_out;

    float *qt, *kt, *v, *attn, *meanv;
    int* del;
    __nv_bfloat16 *wh, *wl, *ah, *al;
    cudaGetSymbolAddress((void**)&qt,    g_qt);
    cudaGetSymbolAddress((void**)&kt,    g_kt);
    cudaGetSymbolAddress((void**)&v,     g_v);
    cudaGetSymbolAddress((void**)&attn,  g_at);
    cudaGetSymbolAddress((void**)&meanv, g_mean);
    cudaGetSymbolAddress((void**)&del,   g_del);
    cudaGetSymbolAddress((void**)&wh,    g_wh);
    cudaGetSymbolAddress((void**)&wl,    g_wl);
    cudaGetSymbolAddress((void**)&ah,    g_ah);
    cudaGetSymbolAddress((void**)&al,    g_al);

    cudaFuncSetAttribute(fuse_kernel,
                         cudaFuncAttributeMaxDynamicSharedMemorySize, 70000);
    cudaFuncSetAttribute(mma_gemm<true>,
                         cudaFuncAttributeMaxDynamicSharedMemorySize, GSM_B);
    cudaFuncSetAttribute(mma_gemm<false>,
                         cudaFuncAttributeMaxDynamicSharedMemorySize, GSM_B);

    const size_t WSZ = 512 * 512;
    dim3 wgrid(16, 16), wblk(32, 8);
    dim3 ggrid(4, M_ROWS / 128);
    const int SPLIT_BLKS = M_ROWS * 512 / 4 / 256;

    tw_init_kernel<<<4, 256>>>();
    wsplit_kernel<<<wgrid, wblk>>>(Wq, wh + 0 * WSZ, wl + 0 * WSZ);
    wsplit_kernel<<<wgrid, wblk>>>(Wk, wh + 1 * WSZ, wl + 1 * WSZ);
    wsplit_kernel<<<wgrid, wblk>>>(Wv, wh + 2 * WSZ, wl + 2 * WSZ);
    wsplit_kernel<<<wgrid, wblk>>>(Wo, wh + 3 * WSZ, wl + 3 * WSZ);

    asplit_kernel<<<SPLIT_BLKS, 256>>>((const float4*)query, (uint2*)ah, (uint2*)al);
    mma_gemm<true ><<<ggrid, 256, GSM_B>>>(ah, al, wh + 0 * WSZ, wl + 0 * WSZ, bq, qt);
    asplit_kernel<<<SPLIT_BLKS, 256>>>((const float4*)key_in, (uint2*)ah, (uint2*)al);
    mma_gemm<true ><<<ggrid, 256, GSM_B>>>(ah, al, wh + 1 * WSZ, wl + 1 * WSZ, bk, kt);
    asplit_kernel<<<SPLIT_BLKS, 256>>>((const float4*)value, (uint2*)ah, (uint2*)al);
    mma_gemm<false><<<ggrid, 256, GSM_B>>>(ah, al, wh + 2 * WSZ, wl + 2 * WSZ, bv, v);

    fftcorr_kernel<<<B_SZ * D_SZ, 256>>>(qt, kt, attn);
    mean_kernel<<<dim3(T_SZ / 256, B_SZ), 256>>>(attn, meanv);
    topk_kernel<<<B_SZ, 256>>>(meanv, del);
    fuse_kernel<<<dim3(T_SZ / 32, B_SZ), 256, 512 * 33 * 4>>>(attn, v, del, ah, al);

    mma_gemm<false><<<ggrid, 256, GSM_B>>>(ah, al, wh + 3 * WSZ, wl + 3 * WSZ, bo, out);
}